// round 2
// baseline (speedup 1.0000x reference)
#include <cuda_runtime.h>
#include <cstdint>

// ---------------------------------------------------------------------------
// SpanRepresentationLayer on GB300
//
//   P[b,s,j] = sum_c X[b,s,c] * WT[c,j],  j = half*T*H + t*H + h   (tf32 GEMM)
//   out[b, n*T+t, h] = P[b,start(n), 0,t,h] + P[b,end(n), 1,t,h] + bias[t,h]
//
// R2: 3-stage GEMM pipeline w/ hoisted smem offsets; smem-staged epilogue
//     (P2 rows shared across the 12 spans that reference them).
// ---------------------------------------------------------------------------

#define BATCH   8
#define SEQ     1024
#define HID     256
#define NTYPES  4
#define DEF_SPAN 12

#define GM (BATCH*SEQ)        // 8192 rows
#define GN (2*NTYPES*HID)     // 2048 cols (half,t,h)
#define GK HID                // 256

#define BM 128
#define BN 128
#define BK 16
#define NKT (GK/BK)           // 16 k-tiles
#define STAGES 3

#define SS 8                  // s-values per epilogue block
#define ROWS2 (SS + DEF_SPAN - 1)   // 19 P2 rows staged
#define EPI_SMEM (ROWS2 * (NTYPES*HID) * 4)   // 77824 bytes

// Static device scratch (no allocations allowed)
__device__ float g_XP[GM*GK];                 // 8 MB permuted/swizzled tf32
__device__ float g_WP[GN*GK];                 // 2 MB
__device__ float g_Y[(size_t)GM*GN];          // 64 MB GEMM output P
__device__ int   g_sstart[16384];
__device__ int   g_send[16384];
__device__ int   g_soff[SEQ+1];

// ---------------------------------------------------------------------------
// helpers
// ---------------------------------------------------------------------------
__device__ __forceinline__ float tf32_rna(float v){
    uint32_t u;
    asm("cvt.rna.tf32.f32 %0, %1;" : "=r"(u) : "f"(v));
    return __uint_as_float(u);
}

__device__ __forceinline__ int swz_idx(int lidx, int k){
    int f = ((lidx & 7) << 4) | (lidx >> 3);
    int chunk = f >> 2;
    return ((chunk ^ (k & 15)) << 2) | (f & 3);
}

__device__ __forceinline__ void cp16(float* dst, const float* src){
    uint32_t d = (uint32_t)__cvta_generic_to_shared(dst);
    asm volatile("cp.async.cg.shared.global [%0], [%1], 16;" :: "r"(d), "l"(src));
}

__device__ __forceinline__ void mma_tf32(float* d, const uint32_t* a, uint32_t b0, uint32_t b1){
    asm volatile(
        "mma.sync.aligned.m16n8k8.row.col.f32.tf32.tf32.f32 "
        "{%0,%1,%2,%3}, {%4,%5,%6,%7}, {%8,%9}, {%0,%1,%2,%3};"
        : "+f"(d[0]), "+f"(d[1]), "+f"(d[2]), "+f"(d[3])
        : "r"(a[0]), "r"(a[1]), "r"(a[2]), "r"(a[3]), "r"(b0), "r"(b1));
}

// ---------------------------------------------------------------------------
// prep kernels
// ---------------------------------------------------------------------------
__global__ void prep_x(const float* __restrict__ X){
    int id = blockIdx.x * blockDim.x + threadIdx.x;
    if (id >= GM*GK) return;
    int m = id >> 8, k = id & 255;
    float v = tf32_rna(X[id]);
    g_XP[((m >> 7) << 15) + k*128 + swz_idx(m & 127, k)] = v;
}

__global__ void prep_w(const float* __restrict__ W){
    int id = blockIdx.x * blockDim.x + threadIdx.x;
    if (id >= GN*GK) return;
    int n = id >> 8, k = id & 255;
    int half = n >> 10, t = (n >> 8) & 3, h = n & 255;
    float v = tf32_rna(W[t*(HID*2*HID) + h*(2*HID) + half*HID + k]);
    g_WP[((n >> 7) << 15) + k*128 + swz_idx(n & 127, k)] = v;
}

// ---------------------------------------------------------------------------
// span table + per-s offsets
// ---------------------------------------------------------------------------
__global__ void build_spans(const int* mptr){
    int s = blockIdx.x * blockDim.x + threadIdx.x;
    if (s >= SEQ) return;
    int m = DEF_SPAN;
    if (mptr){
        int raw = mptr[0];
        if (raw >= 1 && raw <= SEQ) m = raw;
        else {
            float f = __int_as_float(raw);
            if (f >= 1.0f && f <= (float)SEQ) m = (int)f;
        }
    }
    int cnt = min(m, SEQ - s);
    int s0 = SEQ - m;
    long long off;
    if (s <= s0) off = (long long)s * m;
    else {
        int u = s - (s0 + 1);
        off = (long long)(s0 + 1) * m + (long long)u * (m - 1) - (long long)u * (u - 1) / 2;
    }
    g_soff[s] = (int)off;
    if (s == 0){
        long long tot = (long long)m * (SEQ - m + 1) + (long long)m * (m - 1) / 2;
        g_soff[SEQ] = (int)tot;
    }
    for (int i = 0; i < cnt; i++){
        long long o = off + i;
        if (o < 16384){ g_sstart[o] = s; g_send[o] = s + i; }
    }
}

// ---------------------------------------------------------------------------
// GEMM: 128x128x16 tiles, 3-stage cp.async, hoisted smem offsets
// ---------------------------------------------------------------------------
__device__ __forceinline__ void load_stage(float* dA, float* dB,
                                           const float* gA, const float* gB, int kt){
    const float* gAk = gA + kt * (BK*128);
    const float* gBk = gB + kt * (BK*128);
    int tid = threadIdx.x;
    #pragma unroll
    for (int i = 0; i < 2; i++){
        int e = i*256 + tid;
        int kl = e >> 5, p = e & 31;
        cp16(dA + kl*BM + p*4, gAk + kl*128 + p*4);
        cp16(dB + kl*BN + p*4, gBk + kl*128 + p*4);
    }
    asm volatile("cp.async.commit_group;");
}

__global__ __launch_bounds__(256) void gemm_tf32(){
    __shared__ __align__(16) float sA[STAGES][BK*BM];
    __shared__ __align__(16) float sB[STAGES][BK*BN];

    const int tid    = threadIdx.x;
    const int lane   = tid & 31;
    const int wid    = tid >> 5;
    const int warp_m = wid & 3;
    const int warp_n = wid >> 2;

    const float* gA = g_XP + ((size_t)blockIdx.y << 15);
    const float* gB = g_WP + ((size_t)blockIdx.x << 15);

    float acc[2][8][4];
    #pragma unroll
    for (int i = 0; i < 2; i++)
        #pragma unroll
        for (int j = 0; j < 8; j++)
            #pragma unroll
            for (int l = 0; l < 4; l++) acc[i][j][l] = 0.f;

    const int r = lane >> 2, c = lane & 3;
    const int chA = (r << 2) | warp_m;
    const int chB = (r << 2) | (warp_n << 1);

    // Precompute smem fragment byte offsets (constant across k-tiles)
    // A: ka in {c, c+4, c+8, c+12}
    const int aof0 = ( c      *BM + ((chA ^  c      ) << 2)) << 2;
    const int aof1 = ((c + 4) *BM + ((chA ^ (c + 4) ) << 2)) << 2;
    const int aof2 = ((c + 8) *BM + ((chA ^ (c + 8) ) << 2)) << 2;
    const int aof3 = ((c + 12)*BM + ((chA ^ (c + 12)) << 2)) << 2;
    // B: (chB, chB+1) x ka in {c, c+4, c+8, c+12}
    const int bof0 = ( c      *BN + (( chB      ^  c      ) << 2)) << 2;
    const int bof1 = ( c      *BN + (((chB + 1) ^  c      ) << 2)) << 2;
    const int bof2 = ((c + 4) *BN + (( chB      ^ (c + 4) ) << 2)) << 2;
    const int bof3 = ((c + 4) *BN + (((chB + 1) ^ (c + 4) ) << 2)) << 2;
    const int bof4 = ((c + 8) *BN + (( chB      ^ (c + 8) ) << 2)) << 2;
    const int bof5 = ((c + 8) *BN + (((chB + 1) ^ (c + 8) ) << 2)) << 2;
    const int bof6 = ((c + 12)*BN + (( chB      ^ (c + 12)) << 2)) << 2;
    const int bof7 = ((c + 12)*BN + (((chB + 1) ^ (c + 12)) << 2)) << 2;

    // prologue: stages 0 and 1
    load_stage(sA[0], sB[0], gA, gB, 0);
    load_stage(sA[1], sB[1], gA, gB, 1);

    #pragma unroll
    for (int kt = 0; kt < NKT; kt++){
        if (kt < NKT - 1) asm volatile("cp.async.wait_group 1;");
        else              asm volatile("cp.async.wait_group 0;");
        __syncthreads();

        if (kt + 2 < NKT)
            load_stage(sA[(kt+2)%STAGES], sB[(kt+2)%STAGES], gA, gB, kt + 2);

        const char* A  = (const char*)sA[kt % STAGES];
        const char* Bs = (const char*)sB[kt % STAGES];

        #pragma unroll
        for (int ks2 = 0; ks2 < 2; ks2++){
            float4 av0  = *(const float4*)(A  + (ks2 ? aof2 : aof0));
            float4 av1  = *(const float4*)(A  + (ks2 ? aof3 : aof1));
            float4 bv00 = *(const float4*)(Bs + (ks2 ? bof4 : bof0));
            float4 bv01 = *(const float4*)(Bs + (ks2 ? bof5 : bof1));
            float4 bv10 = *(const float4*)(Bs + (ks2 ? bof6 : bof2));
            float4 bv11 = *(const float4*)(Bs + (ks2 ? bof7 : bof3));

            uint32_t a0[4] = {__float_as_uint(av0.x), __float_as_uint(av0.y),
                              __float_as_uint(av1.x), __float_as_uint(av1.y)};
            uint32_t a1[4] = {__float_as_uint(av0.z), __float_as_uint(av0.w),
                              __float_as_uint(av1.z), __float_as_uint(av1.w)};
            uint32_t b0[8] = {__float_as_uint(bv00.x), __float_as_uint(bv00.y),
                              __float_as_uint(bv00.z), __float_as_uint(bv00.w),
                              __float_as_uint(bv01.x), __float_as_uint(bv01.y),
                              __float_as_uint(bv01.z), __float_as_uint(bv01.w)};
            uint32_t b1[8] = {__float_as_uint(bv10.x), __float_as_uint(bv10.y),
                              __float_as_uint(bv10.z), __float_as_uint(bv10.w),
                              __float_as_uint(bv11.x), __float_as_uint(bv11.y),
                              __float_as_uint(bv11.z), __float_as_uint(bv11.w)};
            #pragma unroll
            for (int q = 0; q < 8; q++){
                mma_tf32(acc[0][q], a0, b0[q], b1[q]);
                mma_tf32(acc[1][q], a1, b0[q], b1[q]);
            }
        }
        __syncthreads();
    }

    const int m0 = blockIdx.y*BM + warp_m*32;
    const int n0 = blockIdx.x*BN + warp_n*64;
    #pragma unroll
    for (int mt = 0; mt < 2; mt++){
        #pragma unroll
        for (int q = 0; q < 8; q++){
            int row = m0 + mt*16 + r;
            int col = n0 + q*8 + c*2;
            *(float2*)&g_Y[(size_t)row    *GN + col] = make_float2(acc[mt][q][0], acc[mt][q][1]);
            *(float2*)&g_Y[(size_t)(row+8)*GN + col] = make_float2(acc[mt][q][2], acc[mt][q][3]);
        }
    }
}

// ---------------------------------------------------------------------------
// epilogue v2: block = (batch, 8 consecutive s values) -> ~96 spans.
// P2 rows staged in dynamic smem (19 rows, 76KB), P1 rows via L1 (12x reuse).
// ---------------------------------------------------------------------------
__global__ __launch_bounds__(256) void epilogue2(const float* __restrict__ bias,
                                                 float* __restrict__ out, int N){
    extern __shared__ __align__(16) float sP2[];     // [ROWS2][1024]
    const int b   = blockIdx.y;
    const int s0  = blockIdx.x * SS;
    const int tid = threadIdx.x;

    // stage P2 rows s0 .. s0+ROWS2-1 (half 1 of g_Y rows)
    #pragma unroll
    for (int rr = 0; rr < ROWS2; rr++){
        int row = s0 + rr;
        if (row < SEQ){
            cp16(&sP2[rr*(NTYPES*HID) + tid*4],
                 &g_Y[((size_t)(b*SEQ + row))*GN + NTYPES*HID + tid*4]);
        }
    }
    asm volatile("cp.async.commit_group;");

    const float4 bb = ((const float4*)bias)[tid];
    const int nb = g_soff[s0];
    const int ne = g_soff[min(s0 + SS, SEQ)];
    const float4* P1 = (const float4*)&g_Y[((size_t)b*SEQ)*GN];   // row stride 512 float4
    float4* op = (float4*)out + (size_t)b*N*256 + tid;

    asm volatile("cp.async.wait_group 0;");
    __syncthreads();

    for (int n = nb; n < ne; n++){
        int s = g_sstart[n];
        int e = g_send[n];
        float4 r1 = __ldg(&P1[(size_t)s*512 + tid]);
        float4 r2 = ((const float4*)sP2)[(e - s0)*256 + tid];
        float4 o = make_float4(r1.x + r2.x + bb.x,
                               r1.y + r2.y + bb.y,
                               r1.z + r2.z + bb.z,
                               r1.w + r2.w + bb.w);
        __stcs(op + (size_t)n*256, o);
    }
}

// ---------------------------------------------------------------------------
// launch
// ---------------------------------------------------------------------------
extern "C" void kernel_launch(void* const* d_in, const int* in_sizes, int n_in,
                              void* d_out, int out_size){
    const float* X    = (const float*)d_in[0];
    const float* W    = (const float*)d_in[1];
    const float* bias = (const float*)d_in[2];
    const int*   mptr = (n_in > 3) ? (const int*)d_in[3] : nullptr;

    int N = out_size / (BATCH * NTYPES * HID);

    cudaFuncSetAttribute(epilogue2, cudaFuncAttributeMaxDynamicSharedMemorySize, EPI_SMEM);

    prep_x<<<(GM*GK)/256, 256>>>(X);
    prep_w<<<(GN*GK)/256, 256>>>(W);
    build_spans<<<(SEQ + 255)/256, 256>>>(mptr);

    dim3 gg(GN/BN, GM/BM);
    gemm_tf32<<<gg, 256>>>();

    dim3 ge((SEQ + SS - 1)/SS, BATCH);
    epilogue2<<<ge, 256, EPI_SMEM>>>(bias, (float*)d_out, N);
}